// round 16
// baseline (speedup 1.0000x reference)
#include <cuda_runtime.h>
#include <cuda_fp16.h>
#include <cstdint>
#include <math.h>

// Problem constants
#define BB   8
#define NN   4096
#define KK   16
#define DD   128
#define LL   2
#define NCLS 40
#define BN   (BB*NN)          // 32768
#define MBIG (BN*KK)          // 524288

// ---------------- scratch (device globals; no allocation allowed) -----------
__device__ float  g_x[BN*DD];                 // fp32 residual stream
__device__ __half g_xh[BN*DD];                // fp16 mirror of x
__device__ __half g_qg[BN*DD];                // x @ (Wq G1)
__device__ __half g_kg[BN*DD];                // x @ (Wk G1)
__device__ __half g_v[BN*DD];
__device__ __half g_agg[BN*DD];
__device__ int    g_idx[MBIG];
__device__ float  g_rel[MBIG*3];
__device__ float  g_pmax[BB*32*DD];
// per-layer slots: 0:Wv 1:WqG1 2:WkG1 3:P2 4:P2G1 5:G2 6:Wo  (fp16 [n][k])
__device__ __half g_wimg[14*DD*DD];

// ---------------- helpers ----------------------------------------------------
__device__ __forceinline__ uint32_t h2u(__half2 h) { return *(uint32_t*)&h; }
__device__ __forceinline__ uint32_t smem_u32(const void* p) {
    uint32_t a;
    asm("{ .reg .u64 t; cvta.to.shared.u64 t, %1; cvt.u32.u64 %0, t; }" : "=r"(a) : "l"(p));
    return a;
}
__device__ __forceinline__ void cpa16(uint32_t dst, const void* src) {
    asm volatile("cp.async.ca.shared.global [%0], [%1], 16;" :: "r"(dst), "l"(src));
}
__device__ __forceinline__ void cpa_commit() {
    asm volatile("cp.async.commit_group;" ::: "memory");
}
template<int N> __device__ __forceinline__ void cpa_wait() {
    asm volatile("cp.async.wait_group %0;" :: "n"(N) : "memory");
}
__device__ __forceinline__ void mma16(float* d, const uint32_t* a, const uint32_t* b) {
    asm volatile(
        "mma.sync.aligned.m16n8k16.row.col.f32.f16.f16.f32 "
        "{%0,%1,%2,%3}, {%4,%5,%6,%7}, {%8,%9}, {%0,%1,%2,%3};"
        : "+f"(d[0]), "+f"(d[1]), "+f"(d[2]), "+f"(d[3])
        : "r"(a[0]), "r"(a[1]), "r"(a[2]), "r"(a[3]), "r"(b[0]), "r"(b[1]));
}
__device__ __forceinline__ void ldmx4(uint32_t* r, uint32_t addr) {
    asm volatile("ldmatrix.sync.aligned.m8n8.x4.shared.b16 {%0,%1,%2,%3}, [%4];"
                 : "=r"(r[0]), "=r"(r[1]), "=r"(r[2]), "=r"(r[3]) : "r"(addr));
}

// MMA over one 64-half K chunk using ldmatrix.
__device__ __forceinline__ void mma_chunk16(uint32_t Abase, int sA, int kb,
                                            uint32_t Bbase,
                                            int r0, int c0, int lane,
                                            float acc[4][4][4]) {
    int l7 = lane & 7;
    uint32_t rowA = (uint32_t)(r0 + l7 + ((lane >> 3) & 1) * 8);
    uint32_t colA = (uint32_t)((lane >> 4) * 4);
    uint32_t aAddr = Abase + (rowA * (uint32_t)sA + (uint32_t)kb + colA) * 4u;
    uint32_t rowB = (uint32_t)(c0 + l7 + (lane >> 4) * 8);
    uint32_t colB = (uint32_t)(((lane >> 3) & 1) * 4);
    uint32_t bAddr0 = Bbase + (rowB * 36u + colB) * 4u;
    uint32_t bAddr1 = bAddr0 + 16u * 36u * 4u;
    uint32_t aStepM = (uint32_t)(16 * sA * 4);

#pragma unroll
    for (int ks = 0; ks < 4; ks++) {
        uint32_t af[4][4], bf[2][4];
#pragma unroll
        for (int mf = 0; mf < 4; mf++)
            ldmx4(af[mf], aAddr + (uint32_t)mf * aStepM + (uint32_t)(ks * 32));
        ldmx4(bf[0], bAddr0 + (uint32_t)(ks * 32));
        ldmx4(bf[1], bAddr1 + (uint32_t)(ks * 32));
#pragma unroll
        for (int mf = 0; mf < 4; mf++) {
            mma16(acc[mf][0], af[mf], &bf[0][0]);
            mma16(acc[mf][1], af[mf], &bf[0][2]);
            mma16(acc[mf][2], af[mf], &bf[1][0]);
            mma16(acc[mf][3], af[mf], &bf[1][2]);
        }
    }
}

// B stage loader: Bimg [n=128][k=128] fp16, chunk k0 (halves), stage stride 36 b32
__device__ __forceinline__ void loadB(uint32_t bsm, const __half* __restrict__ Bimg,
                                      int k0, int t) {
#pragma unroll
    for (int i = 0; i < 4; i++) {
        int idx = t + i*256;
        int n = idx >> 3, seg = idx & 7;
        cpa16(bsm + (uint32_t)(n*144 + seg*16), Bimg + (size_t)n*128 + k0 + seg*8);
    }
}
// A stage loader from fp16 global [m][128]
__device__ __forceinline__ void loadA(uint32_t asmb, const __half* __restrict__ A,
                                      int mBase, int k0, int t) {
#pragma unroll
    for (int i = 0; i < 4; i++) {
        int idx = t + i*256;
        int row = idx >> 3, seg = idx & 7;
        cpa16(asmb + (uint32_t)(row*144 + seg*16), A + (size_t)(mBase+row)*128 + k0 + seg*8);
    }
}

// ---------------- weight image prep (straight transposes) --------------------
__global__ void prep_all(const float* __restrict__ Wv, const float* __restrict__ P2,
                         const float* __restrict__ G2, const float* __restrict__ Wo,
                         __half* __restrict__ dst) {
    int y = blockIdx.y;                  // 0..4*LL-1
    int l = y >> 2, w = y & 3;
    const float* src;
    int slot;
    switch (w) {
        case 0: src = Wv; slot = 0; break;
        case 1: src = P2; slot = 3; break;
        case 2: src = G2; slot = 5; break;
        default: src = Wo; slot = 6; break;
    }
    src += (size_t)l*DD*DD;
    int n = blockIdx.x, k = threadIdx.x;
    dst[(size_t)(l*7 + slot)*16384 + n*128 + k] = __float2half(src[k*128 + n]);
}

// ---------------- composite weight prep: (A @ G1) images ---------------------
__global__ void prep_combo(const float* __restrict__ Wq, const float* __restrict__ Wk,
                           const float* __restrict__ P2, const float* __restrict__ G1,
                           __half* __restrict__ dst) {
    int n = blockIdx.x;
    int y = blockIdx.y;
    int l = y / 3, w = y % 3;
    const float* A = (w == 0 ? Wq : (w == 1 ? Wk : P2)) + (size_t)l*DD*DD;
    const float* B = G1 + (size_t)l*DD*DD;
    __shared__ float Bcol[DD];
    int k = threadIdx.x;
    Bcol[k] = B[k*DD + n];
    __syncthreads();
    float acc = 0.f;
#pragma unroll 8
    for (int c = 0; c < DD; c++) acc += A[k*DD + c] * Bcol[c];
    int slot = (w == 0 ? 1 : (w == 1 ? 2 : 4));
    dst[(size_t)(l*7 + slot)*16384 + n*DD + k] = __float2half(acc);
}

// ======================= fused GEMM: one A tile, 3 weights ==================
#define QKV_SMEM (6*4608*4)
__global__ __launch_bounds__(256, 2) void qkv3(const __half* __restrict__ A,
                                               const __half* __restrict__ B0,
                                               const __half* __restrict__ B1,
                                               const __half* __restrict__ B2,
                                               __half* __restrict__ O0,
                                               __half* __restrict__ O1,
                                               __half* __restrict__ O2) {
    extern __shared__ float sm[];
    uint32_t* Ast[2] = { (uint32_t*)sm, (uint32_t*)sm + 4608 };
    uint32_t* Bst[2] = { (uint32_t*)sm + 9216, (uint32_t*)sm + 13824 };
    int t = threadIdx.x;
    int mBase = blockIdx.x * 128;
    int lane = t & 31, wid = t >> 5;
    int r0 = (wid & 1) * 64, c0 = (wid >> 1) * 32;
    int ar = lane >> 2, ak = lane & 3;

    const __half* Bimg[3] = { B0, B1, B2 };
    __half* Out[3] = { O0, O1, O2 };
    uint32_t uA0 = smem_u32(Ast[0]), uA1 = smem_u32(Ast[1]);
    uint32_t uB0 = smem_u32(Bst[0]), uB1 = smem_u32(Bst[1]);

    loadA(uA0, A, mBase, 0, t);
    loadA(uA1, A, mBase, 64, t);
    loadB(uB0, B0, 0, t);
    cpa_commit();
    loadB(uB1, B0, 64, t);
    cpa_commit();

#pragma unroll
    for (int w = 0; w < 3; w++) {
        float acc[4][4][4] = {};
        cpa_wait<1>(); __syncthreads();
        mma_chunk16(uA0, 36, 0, uB0, r0, c0, lane, acc);
        __syncthreads();
        if (w < 2) { loadB(uB0, Bimg[w+1], 0, t); cpa_commit(); }
        if (w < 2) cpa_wait<1>(); else cpa_wait<0>();
        __syncthreads();
        mma_chunk16(uA1, 36, 0, uB1, r0, c0, lane, acc);
        __syncthreads();
        if (w < 2) { loadB(uB1, Bimg[w+1], 64, t); cpa_commit(); }
        __half* C = Out[w];
#pragma unroll
        for (int mf = 0; mf < 4; mf++)
#pragma unroll
        for (int nf = 0; nf < 4; nf++) {
            int r = mBase + r0 + mf*16 + ar;
            int c = c0 + nf*8 + 2*ak;
            *(__half2*)(C + (size_t)r*128 + c) =
                __floats2half2_rn(acc[mf][nf][0], acc[mf][nf][1]);
            *(__half2*)(C + (size_t)(r+8)*128 + c) =
                __floats2half2_rn(acc[mf][nf][2], acc[mf][nf][3]);
        }
    }
}

// ======================= residual GEMM: Cf = Res + A@W, Ch = half(Cf) =======
#define HG_SMEM (4*4608*4)
__global__ __launch_bounds__(256, 2) void hgemm_res(const __half* __restrict__ A,
                                                    const __half* __restrict__ Bimg,
                                                    __half* __restrict__ Ch,
                                                    float* __restrict__ Cf,
                                                    const float* __restrict__ Res) {
    extern __shared__ float sm[];
    uint32_t* Ast[2] = { (uint32_t*)sm, (uint32_t*)sm + 4608 };
    uint32_t* Bst[2] = { (uint32_t*)sm + 9216, (uint32_t*)sm + 13824 };
    int t = threadIdx.x;
    int mBase = blockIdx.x * 128;
    uint32_t uA0 = smem_u32(Ast[0]), uA1 = smem_u32(Ast[1]);
    uint32_t uB0 = smem_u32(Bst[0]), uB1 = smem_u32(Bst[1]);

    loadA(uA0, A, mBase, 0, t);
    loadB(uB0, Bimg, 0, t);
    cpa_commit();
    loadA(uA1, A, mBase, 64, t);
    loadB(uB1, Bimg, 64, t);
    cpa_commit();

    int lane = t & 31, wid = t >> 5;
    int r0 = (wid & 1) * 64, c0 = (wid >> 1) * 32;
    int ar = lane >> 2, ak = lane & 3;
    float acc[4][4][4] = {};

    cpa_wait<1>(); __syncthreads();
    mma_chunk16(uA0, 36, 0, uB0, r0, c0, lane, acc);
    cpa_wait<0>(); __syncthreads();
    mma_chunk16(uA1, 36, 0, uB1, r0, c0, lane, acc);

#pragma unroll
    for (int mf = 0; mf < 4; mf++)
#pragma unroll
    for (int nf = 0; nf < 4; nf++) {
        int r = mBase + r0 + mf*16 + ar;
        int c = c0 + nf*8 + 2*ak;
        float2 v0 = make_float2(acc[mf][nf][0], acc[mf][nf][1]);
        float2 v1 = make_float2(acc[mf][nf][2], acc[mf][nf][3]);
        float2 a0 = *(const float2*)(Res + (size_t)r*128 + c);
        float2 a1 = *(const float2*)(Res + (size_t)(r+8)*128 + c);
        v0.x += a0.x; v0.y += a0.y; v1.x += a1.x; v1.y += a1.y;
        *(float2*)(Cf + (size_t)r*128 + c) = v0;
        *(float2*)(Cf + (size_t)(r+8)*128 + c) = v1;
        *(__half2*)(Ch + (size_t)r*128 + c) = __floats2half2_rn(v0.x, v0.y);
        *(__half2*)(Ch + (size_t)(r+8)*128 + c) = __floats2half2_rn(v1.x, v1.y);
    }
}

// ======== fused per-neighbor block (linearity-restructured) =================
#define FU_SMEM (27136*4)
__global__ __launch_bounds__(256, 2) void pt_fused(const float* __restrict__ P1L,
                                                   const __half* __restrict__ P2img,
                                                   const __half* __restrict__ P21img,
                                                   const __half* __restrict__ G2img,
                                                   int mOff) {
    extern __shared__ float sm[];
    uint32_t* DlH = (uint32_t*)sm;
    uint32_t* Ast[2] = { (uint32_t*)(sm + 8704), (uint32_t*)(sm + 13312) };
    uint32_t* Bst[2] = { (uint32_t*)(sm + 17920), (uint32_t*)(sm + 22528) };
    float*    Ls = sm + 8704;

    __shared__ int     rowK[128];
    __shared__ __half2 relH[128][4];     // (x,x),(y,y),(z,z),pad
    __shared__ __half2 P1h[3][64];

    int t = threadIdx.x;
    int mBase = (blockIdx.x + mOff) * 128;
    int lane = t & 31, wid = t >> 5;
    int r0 = (wid & 1) * 64, c0 = (wid >> 1) * 32;
    int ar = lane >> 2, ak = lane & 3;
    uint32_t uA0 = smem_u32(Ast[0]), uA1 = smem_u32(Ast[1]);
    uint32_t uB0 = smem_u32(Bst[0]), uB1 = smem_u32(Bst[1]);
    uint32_t uHu = uA0;

    if (t < 128) {
        int m = mBase + t;
        rowK[t] = ((m >> 4) >> 12) * NN + g_idx[m];
        relH[t][0] = __float2half2_rn(g_rel[(size_t)m*3+0]);
        relH[t][1] = __float2half2_rn(g_rel[(size_t)m*3+1]);
        relH[t][2] = __float2half2_rn(g_rel[(size_t)m*3+2]);
    }
    if (t < 192) {
        int coord = t / 64, j = t % 64;
        P1h[coord][j] = __floats2half2_rn(P1L[coord*128 + 2*j], P1L[coord*128 + 2*j + 1]);
    }

    loadB(uB0, P2img, 0, t);  cpa_commit();
    loadB(uB1, P2img, 64, t); cpa_commit();
    __syncthreads();

    // ---- build A_pair = relu(rel @ P1) into Ast[0..1] (half2 math) ----
    {
        const __half2 z2 = __floats2half2_rn(0.f, 0.f);
#pragma unroll
        for (int st = 0; st < 2; st++) {
#pragma unroll
            for (int i = 0; i < 16; i++) {
                int idx = t + i*256;
                int row = idx >> 5, j = idx & 31;
                int pj = st*32 + j;
                __half2 v = __hmul2(relH[row][0], P1h[0][pj]);
                v = __hfma2(relH[row][1], P1h[1][pj], v);
                v = __hfma2(relH[row][2], P1h[2][pj], v);
                v = __hmax2(v, z2);
                Ast[st][row*36 + j] = h2u(v);
            }
        }
    }

    float acc[4][4][4] = {};

    // ================= GEMM A: delta = A_pair @ P2 -> DlH ===================
    cpa_wait<1>(); __syncthreads();
    mma_chunk16(uA0, 36, 0, uB0, r0, c0, lane, acc);
    __syncthreads();
    loadB(uB0, P21img, 0, t); cpa_commit();
    cpa_wait<1>(); __syncthreads();
    mma_chunk16(uA1, 36, 0, uB1, r0, c0, lane, acc);
    __syncthreads();
    loadB(uB1, P21img, 64, t); cpa_commit();
#pragma unroll
    for (int mf = 0; mf < 4; mf++)
#pragma unroll
    for (int nf = 0; nf < 4; nf++) {
        int r = r0 + mf*16 + ar;
        int cb = (c0 + nf*8) >> 1;
        DlH[r*68 + cb + ak] = h2u(__floats2half2_rn(acc[mf][nf][0], acc[mf][nf][1]));
        DlH[(r+8)*68 + cb + ak] = h2u(__floats2half2_rn(acc[mf][nf][2], acc[mf][nf][3]));
        acc[mf][nf][0] = acc[mf][nf][1] = acc[mf][nf][2] = acc[mf][nf][3] = 0.f;
    }

    // ================= GEMM B: dg = A_pair @ (P2 G1); h2 in epilogue ========
    cpa_wait<1>(); __syncthreads();
    mma_chunk16(uA0, 36, 0, uB0, r0, c0, lane, acc);
    __syncthreads();
    loadB(uB0, G2img, 0, t); cpa_commit();
    cpa_wait<1>(); __syncthreads();
    mma_chunk16(uA1, 36, 0, uB1, r0, c0, lane, acc);
    __syncthreads();
    loadB(uB1, G2img, 64, t); cpa_commit();
    {
        uint32_t* Hu = (uint32_t*)Ast[0];
#pragma unroll
        for (int mf = 0; mf < 4; mf++)
#pragma unroll
        for (int nf = 0; nf < 4; nf++) {
            int r = r0 + mf*16 + ar;
            int c = c0 + nf*8 + 2*ak;
            int bn0 = (mBase + r) >> 4, bn1 = (mBase + r + 8) >> 4;
            __half2 q0 = *(const __half2*)(g_qg + (size_t)bn0*128 + c);
            __half2 k0h = *(const __half2*)(g_kg + (size_t)rowK[r]*128 + c);
            __half2 q1 = *(const __half2*)(g_qg + (size_t)bn1*128 + c);
            __half2 k1h = *(const __half2*)(g_kg + (size_t)rowK[r+8]*128 + c);
            float h00 = fmaxf(acc[mf][nf][0] + __half2float(q0.x) - __half2float(k0h.x), 0.f);
            float h01 = fmaxf(acc[mf][nf][1] + __half2float(q0.y) - __half2float(k0h.y), 0.f);
            float h10 = fmaxf(acc[mf][nf][2] + __half2float(q1.x) - __half2float(k1h.x), 0.f);
            float h11 = fmaxf(acc[mf][nf][3] + __half2float(q1.y) - __half2float(k1h.y), 0.f);
            int cb = (c0 + nf*8) >> 1;
            Hu[r*68 + cb + ak] = h2u(__floats2half2_rn(h00, h01));
            Hu[(r+8)*68 + cb + ak] = h2u(__floats2half2_rn(h10, h11));
            acc[mf][nf][0] = acc[mf][nf][1] = acc[mf][nf][2] = acc[mf][nf][3] = 0.f;
        }
    }
    __syncthreads();

    // ================= GEMM C: logits = h2 @ G2 =============================
    cpa_wait<1>(); __syncthreads();
    mma_chunk16(uHu, 68, 0,  uB0, r0, c0, lane, acc);
    cpa_wait<0>(); __syncthreads();
    mma_chunk16(uHu, 68, 32, uB1, r0, c0, lane, acc);
    __syncthreads();
#pragma unroll
    for (int mf = 0; mf < 4; mf++)
#pragma unroll
    for (int nf = 0; nf < 4; nf++) {
        int r = r0 + mf*16 + ar;
        int c = c0 + nf*8 + 2*ak;
        Ls[r*132 + c]       = acc[mf][nf][0];
        Ls[r*132 + c+1]     = acc[mf][nf][1];
        Ls[(r+8)*132 + c]   = acc[mf][nf][2];
        Ls[(r+8)*132 + c+1] = acc[mf][nf][3];
    }
    __syncthreads();

    // ================= softmax over K + aggregate (2 dims/thread) ===========
    const __half* DlHh = (const __half*)DlH;
    for (int it = t; it < 512; it += 256) {
        int p = it >> 6, dd = (it & 63) * 2;
        float2 lo[KK];
        float mx0 = -3.4e38f, mx1 = -3.4e38f;
#pragma unroll
        for (int k = 0; k < KK; k++) {
            lo[k].x = Ls[(p*16 + k)*132 + dd];
            lo[k].y = Ls[(p*16 + k)*132 + dd + 1];
            mx0 = fmaxf(mx0, lo[k].x);
            mx1 = fmaxf(mx1, lo[k].y);
        }
        float s0 = 0.f, s1 = 0.f;
#pragma unroll
        for (int k = 0; k < KK; k++) {
            lo[k].x = expf(lo[k].x - mx0); s0 += lo[k].x;
            lo[k].y = expf(lo[k].y - mx1); s1 += lo[k].y;
        }
        float i0 = 1.f / s0, i1 = 1.f / s1;
        float a0 = 0.f, a1 = 0.f;
#pragma unroll
        for (int k = 0; k < KK; k++) {
            __half2 vj = *(const __half2*)(g_v + (size_t)rowK[p*16+k]*128 + dd);
            __half2 dl = *(const __half2*)(DlHh + (p*16 + k)*136 + dd);
            a0 += lo[k].x * i0 * (__half2float(vj.x) + __half2float(dl.x));
            a1 += lo[k].y * i1 * (__half2float(vj.y) + __half2float(dl.y));
        }
        *(__half2*)(g_agg + (size_t)((mBase >> 4) + p)*128 + dd) = __floats2half2_rn(a0, a1);
    }
}

// ---------------- embedding: x = relu(features @ W_embed) -------------------
__global__ void embed_k(const float* __restrict__ f, const float* __restrict__ W) {
    int m = blockIdx.x;
    int d = threadIdx.x;
    float f0 = f[m*3+0], f1 = f[m*3+1], f2 = f[m*3+2];
    float v = fmaxf(f0*W[d] + f1*W[DD+d] + f2*W[2*DD+d], 0.f);
    g_x[m*DD + d] = v;
    g_xh[m*DD + d] = __float2half(v);
}

// ---------------- kNN: 128-bin histogram select, per-batch launch -----------
#define KQ 32
#define NBIN 128
__global__ __launch_bounds__(256) void knn_k(const float* __restrict__ pos, int b) {
    __shared__ char smk[33280];
    float4*   sp   = (float4*)smk;                  // [1024] tile (16KB)
    uint32_t* hist = (uint32_t*)(smk + 16384);      // [32*128] (16KB)
    float*    bmD  = (float*)smk;                   // alias sp   [256*16]
    int*      bmI  = (int*)(smk + 16384);           // alias hist [256*16]
    uint32_t* qcnt = (uint32_t*)(smk + 32768);      // [32]
    int*      Tbin = (int*)(smk + 32896);           // [32]
    int*      Rrem = (int*)(smk + 33024);           // [32]

    int t = threadIdx.x;
    int q = t >> 3, sub = t & 7;
    int qg = blockIdx.x*KQ + q;
    const float* pb = pos + (size_t)b*NN*3;
    float px = pb[qg*3+0], py = pb[qg*3+1], pz = pb[qg*3+2];
    float sqi = px*px + py*py + pz*pz;

    for (int i = t; i < KQ*NBIN; i += 256) hist[i] = 0;
    if (t < KQ) qcnt[t] = 0;
    __syncthreads();

    // ---- pass A: histogram (branchless) ----
    for (int j0 = 0; j0 < NN; j0 += 1024) {
        for (int i = t; i < 1024; i += 256) {
            float x = pb[(j0+i)*3+0], y = pb[(j0+i)*3+1], z = pb[(j0+i)*3+2];
            sp[i] = make_float4(-2.f*x, -2.f*y, -2.f*z, x*x + y*y + z*z);
        }
        __syncthreads();
#pragma unroll 4
        for (int s = 0; s < 1024; s += 8) {
            float4 c = sp[s + sub];
            float d2 = fmaf(px, c.x, c.w);
            d2 = fmaf(py, c.y, d2);
            d2 = fmaf(pz, c.z, d2);
            d2 = fmaxf(d2 + sqi, 0.f);
            int bin = (int)(__float_as_uint(d2) >> 20) - 952;
            bin = bin < 0 ? 0 : (bin > NBIN-1 ? NBIN-1 : bin);
            atomicAdd(&hist[q*NBIN + bin], 1u);
        }
        __syncthreads();
    }

    // ---- per-query threshold ----
    if (t < KQ) {
        int cum = 0, T = NBIN-1;
        for (int bn = 0; bn < NBIN; bn++) {
            int c = (int)hist[t*NBIN + bn];
            if (cum + c >= KK) { T = bn; break; }
            cum += c;
        }
        Tbin[t] = T;
        Rrem[t] = KK - cum;
    }
    __syncthreads();

    int T = Tbin[q];
    float bd[KK]; int bi[KK];
#pragma unroll
    for (int k = 0; k < KK; k++) { bd[k] = 3.4e38f; bi[k] = -1; }
    float worst = 3.4e38f; int wslot = 0;
    int base = (b*NN + qg)*KK;

    // ---- pass B: emit below-threshold; collect boundary top-16 ----
    for (int j0 = 0; j0 < NN; j0 += 1024) {
        for (int i = t; i < 1024; i += 256) {
            float x = pb[(j0+i)*3+0], y = pb[(j0+i)*3+1], z = pb[(j0+i)*3+2];
            sp[i] = make_float4(-2.f*x, -2.f*y, -2.f*z, x*x + y*y + z*z);
        }
        __syncthreads();
#pragma unroll 4
        for (int s = 0; s < 1024; s += 8) {
            float4 c = sp[s + sub];
            float d2 = fmaf(px, c.x, c.w);
            d2 = fmaf(py, c.y, d2);
            d2 = fmaf(pz, c.z, d2);
            d2 = fmaxf(d2 + sqi, 0.f);
            int bin = (int)(__float_as_uint(d2) >> 20) - 952;
            bin = bin < 0 ? 0 : (bin > NBIN-1 ? NBIN-1 : bin);
            if (bin < T) {
                uint32_t slot = atomicAdd(&qcnt[q], 1u);
                int j = j0 + s + sub;
                g_idx[base + slot] = j;
                g_rel[(size_t)(base+slot)*3+0] = fmaf(0.5f, c.x, px);
                g_rel[(size_t)(base+slot)*3+1] = fmaf(0.5f, c.y, py);
                g_rel[(size_t)(base+slot)*3+2] = fmaf(0.5f, c.z, pz);
            } else if (bin == T && d2 < worst) {
                bd[wslot] = d2; bi[wslot] = j0 + s + sub;
                worst = bd[0]; wslot = 0;
#pragma unroll
                for (int k = 1; k < KK; k++)
                    if (bd[k] > worst) { worst = bd[k]; wslot = k; }
            }
        }
        __syncthreads();
    }

    // ---- publish boundary lists (alias over sp/hist, both dead) ----
#pragma unroll
    for (int k = 0; k < KK; k++) {
        bmD[t*KK + k] = bd[k];
        bmI[t*KK + k] = bi[k];
    }
    __syncthreads();

    // ---- per-query merge: take R smallest of the 8 sub-lists (128 entries) --
    if (t < KQ) {
        int R = Rrem[t];
        int start = (int)qcnt[t];
        int qg2 = blockIdx.x*KQ + t;
        float qx = pb[qg2*3+0], qy = pb[qg2*3+1], qz = pb[qg2*3+2];
        int base2 = (b*NN + qg2)*KK;
        float* D = &bmD[t*128];
        int*   I = &bmI[t*128];
        for (int r = 0; r < R; r++) {
            float best = D[0]; int bl = 0;
#pragma unroll 8
            for (int k = 1; k < 128; k++)
                if (D[k] < best) { best = D[k]; bl = k; }
            int j = I[bl];
            D[bl] = 3.4e38f;
            g_idx[base2 + start + r] = j;
            g_rel[(size_t)(base2+start+r)*3+0] = qx - pb[j*3+0];
            g_rel[(size_t)(base2+start+r)*3+1] = qy - pb[j*3+1];
            g_rel[(size_t)(base2+start+r)*3+2] = qz - pb[j*3+2];
        }
    }
}

// ---------------- global max pool (partial) ---------------------------------
__global__ void poolmax_k() {
    int b  = blockIdx.x >> 5;
    int ch = blockIdx.x & 31;
    int d  = threadIdx.x;
    float m = -3.4e38f;
    for (int n = ch*128; n < ch*128 + 128; n++)
        m = fmaxf(m, g_x[((size_t)b*NN + n)*DD + d]);
    g_pmax[(size_t)blockIdx.x*DD + d] = m;
}

// ---------------- classifier head -------------------------------------------
__global__ void cls_k(const float* __restrict__ Wc1, const float* __restrict__ Wc2,
                      float* __restrict__ out) {
    int b = blockIdx.x;
    int d = threadIdx.x;
    __shared__ float pooled[DD];
    __shared__ float h[DD];
    float m = -3.4e38f;
    for (int ch = 0; ch < 32; ch++)
        m = fmaxf(m, g_pmax[((size_t)b*32 + ch)*DD + d]);
    pooled[d] = m;
    __syncthreads();
    float acc = 0.f;
    for (int c = 0; c < DD; c++) acc += pooled[c]*Wc1[c*DD + d];
    h[d] = fmaxf(acc, 0.f);
    __syncthreads();
    if (d < NCLS) {
        float o = 0.f;
        for (int c = 0; c < DD; c++) o += h[c]*Wc2[c*NCLS + d];
        out[b*NCLS + d] = o;
    }
}

// ---------------- launch -----------------------------------------------------
extern "C" void kernel_launch(void* const* d_in, const int* in_sizes, int n_in,
                              void* d_out, int out_size) {
    const float* features = (const float*)d_in[0];
    const float* pos      = (const float*)d_in[1];
    const float* W_embed  = (const float*)d_in[2];
    const float* Wq       = (const float*)d_in[3];
    const float* Wk       = (const float*)d_in[4];
    const float* Wv       = (const float*)d_in[5];
    const float* P1       = (const float*)d_in[6];
    const float* P2       = (const float*)d_in[7];
    const float* G1       = (const float*)d_in[8];
    const float* G2       = (const float*)d_in[9];
    const float* Wo       = (const float*)d_in[10];
    const float* Wc1      = (const float*)d_in[11];
    const float* Wc2      = (const float*)d_in[12];
    float* out = (float*)d_out;

    static float  *px = nullptr;
    static __half *pxh=nullptr, *pqg=nullptr, *pkg=nullptr, *pv=nullptr,
                  *pagg=nullptr, *pwimg=nullptr;
    static cudaStream_t sKnn = nullptr;
    static cudaEvent_t evFork = nullptr, evKnnB[BB];
    if (!px) {
        cudaGetSymbolAddress((void**)&px,   g_x);
        cudaGetSymbolAddress((void**)&pxh,  g_xh);
        cudaGetSymbolAddress((void**)&pqg,  g_qg);
        cudaGetSymbolAddress((void**)&pkg,  g_kg);
        cudaGetSymbolAddress((void**)&pv,   g_v);
        cudaGetSymbolAddress((void**)&pagg, g_agg);
        cudaGetSymbolAddress((void**)&pwimg,g_wimg);
        cudaFuncSetAttribute(qkv3,      cudaFuncAttributeMaxDynamicSharedMemorySize, QKV_SMEM);
        cudaFuncSetAttribute(hgemm_res, cudaFuncAttributeMaxDynamicSharedMemorySize, HG_SMEM);
        cudaFuncSetAttribute(pt_fused,  cudaFuncAttributeMaxDynamicSharedMemorySize, FU_SMEM);
        cudaStreamCreateWithFlags(&sKnn, cudaStreamNonBlocking);
        cudaEventCreateWithFlags(&evFork, cudaEventDisableTiming);
        for (int b = 0; b < BB; b++)
            cudaEventCreateWithFlags(&evKnnB[b], cudaEventDisableTiming);
    }

    // fork: per-batch knn runs concurrently with head chain + layer-0 pt_fused
    cudaEventRecord(evFork, 0);
    cudaStreamWaitEvent(sKnn, evFork, 0);
    for (int b = 0; b < BB; b++) {
        knn_k<<<dim3(NN/KQ, 1), 256, 0, sKnn>>>(pos, b);
        cudaEventRecord(evKnnB[b], sKnn);
    }

    prep_all<<<dim3(128, 4*LL), 128>>>(Wv, P2, G2, Wo, pwimg);
    prep_combo<<<dim3(128, 3*LL), 128>>>(Wq, Wk, P2, G1, pwimg);
    embed_k<<<BN, DD>>>(features, W_embed);

    for (int l = 0; l < LL; l++) {
        const float*  P1L = P1 + (size_t)l*3*DD;
        const __half* img = pwimg + (size_t)l*7*16384;

        qkv3<<<BN/128, 256, QKV_SMEM>>>(pxh, img + 0*16384, img + 1*16384, img + 2*16384,
                                        pv, pqg, pkg);
        if (l == 0) {
            // batch-chunked: each chunk gated on its own knn event
            for (int b = 0; b < BB; b++) {
                cudaStreamWaitEvent(0, evKnnB[b], 0);
                pt_fused<<<MBIG/128/BB, 256, FU_SMEM>>>(P1L, img + 3*16384,
                                                        img + 4*16384, img + 5*16384,
                                                        b * (MBIG/128/BB));
            }
        } else {
            pt_fused<<<MBIG/128, 256, FU_SMEM>>>(P1L, img + 3*16384,
                                                 img + 4*16384, img + 5*16384, 0);
        }
        hgemm_res<<<BN/128, 256, HG_SMEM>>>(pagg, img + 6*16384, pxh, px, px);
    }

    poolmax_k<<<BB*32, DD>>>();
    cls_k<<<BB, DD>>>(Wc1, Wc2, out);
}

// round 17
// speedup vs baseline: 1.4619x; 1.4619x over previous
#include <cuda_runtime.h>
#include <cuda_fp16.h>
#include <cstdint>
#include <math.h>

// Problem constants
#define BB   8
#define NN   4096
#define KK   16
#define DD   128
#define LL   2
#define NCLS 40
#define BN   (BB*NN)          // 32768
#define MBIG (BN*KK)          // 524288

// ---------------- scratch (device globals; no allocation allowed) -----------
__device__ float  g_x[BN*DD];                 // fp32 residual stream
__device__ __half g_xh[BN*DD];                // fp16 mirror of x
__device__ __half g_qg[BN*DD];                // x @ (Wq G1)
__device__ __half g_kg[BN*DD];                // x @ (Wk G1)
__device__ __half g_v[BN*DD];
__device__ __half g_agg[BN*DD];
__device__ int    g_idx[MBIG];
__device__ float  g_rel[MBIG*3];
__device__ float  g_pmax[BB*32*DD];
// per-layer slots: 0:Wv 1:WqG1 2:WkG1 3:P2 4:P2G1 5:G2 6:Wo  (fp16 [n][k])
__device__ __half g_wimg[14*DD*DD];

// ---------------- helpers ----------------------------------------------------
__device__ __forceinline__ uint32_t h2u(__half2 h) { return *(uint32_t*)&h; }
__device__ __forceinline__ uint32_t smem_u32(const void* p) {
    uint32_t a;
    asm("{ .reg .u64 t; cvta.to.shared.u64 t, %1; cvt.u32.u64 %0, t; }" : "=r"(a) : "l"(p));
    return a;
}
__device__ __forceinline__ void cpa16(uint32_t dst, const void* src) {
    asm volatile("cp.async.ca.shared.global [%0], [%1], 16;" :: "r"(dst), "l"(src));
}
__device__ __forceinline__ void cpa_commit() {
    asm volatile("cp.async.commit_group;" ::: "memory");
}
template<int N> __device__ __forceinline__ void cpa_wait() {
    asm volatile("cp.async.wait_group %0;" :: "n"(N) : "memory");
}
__device__ __forceinline__ void mma16(float* d, const uint32_t* a, const uint32_t* b) {
    asm volatile(
        "mma.sync.aligned.m16n8k16.row.col.f32.f16.f16.f32 "
        "{%0,%1,%2,%3}, {%4,%5,%6,%7}, {%8,%9}, {%0,%1,%2,%3};"
        : "+f"(d[0]), "+f"(d[1]), "+f"(d[2]), "+f"(d[3])
        : "r"(a[0]), "r"(a[1]), "r"(a[2]), "r"(a[3]), "r"(b[0]), "r"(b[1]));
}
__device__ __forceinline__ void ldmx4(uint32_t* r, uint32_t addr) {
    asm volatile("ldmatrix.sync.aligned.m8n8.x4.shared.b16 {%0,%1,%2,%3}, [%4];"
                 : "=r"(r[0]), "=r"(r[1]), "=r"(r[2]), "=r"(r[3]) : "r"(addr));
}

// MMA over one 64-half K chunk using ldmatrix.
__device__ __forceinline__ void mma_chunk16(uint32_t Abase, int sA, int kb,
                                            uint32_t Bbase,
                                            int r0, int c0, int lane,
                                            float acc[4][4][4]) {
    int l7 = lane & 7;
    uint32_t rowA = (uint32_t)(r0 + l7 + ((lane >> 3) & 1) * 8);
    uint32_t colA = (uint32_t)((lane >> 4) * 4);
    uint32_t aAddr = Abase + (rowA * (uint32_t)sA + (uint32_t)kb + colA) * 4u;
    uint32_t rowB = (uint32_t)(c0 + l7 + (lane >> 4) * 8);
    uint32_t colB = (uint32_t)(((lane >> 3) & 1) * 4);
    uint32_t bAddr0 = Bbase + (rowB * 36u + colB) * 4u;
    uint32_t bAddr1 = bAddr0 + 16u * 36u * 4u;
    uint32_t aStepM = (uint32_t)(16 * sA * 4);

#pragma unroll
    for (int ks = 0; ks < 4; ks++) {
        uint32_t af[4][4], bf[2][4];
#pragma unroll
        for (int mf = 0; mf < 4; mf++)
            ldmx4(af[mf], aAddr + (uint32_t)mf * aStepM + (uint32_t)(ks * 32));
        ldmx4(bf[0], bAddr0 + (uint32_t)(ks * 32));
        ldmx4(bf[1], bAddr1 + (uint32_t)(ks * 32));
#pragma unroll
        for (int mf = 0; mf < 4; mf++) {
            mma16(acc[mf][0], af[mf], &bf[0][0]);
            mma16(acc[mf][1], af[mf], &bf[0][2]);
            mma16(acc[mf][2], af[mf], &bf[1][0]);
            mma16(acc[mf][3], af[mf], &bf[1][2]);
        }
    }
}

// B stage loader: Bimg [n=128][k=128] fp16, chunk k0 (halves), stage stride 36 b32
__device__ __forceinline__ void loadB(uint32_t bsm, const __half* __restrict__ Bimg,
                                      int k0, int t) {
#pragma unroll
    for (int i = 0; i < 4; i++) {
        int idx = t + i*256;
        int n = idx >> 3, seg = idx & 7;
        cpa16(bsm + (uint32_t)(n*144 + seg*16), Bimg + (size_t)n*128 + k0 + seg*8);
    }
}
// A stage loader from fp16 global [m][128]
__device__ __forceinline__ void loadA(uint32_t asmb, const __half* __restrict__ A,
                                      int mBase, int k0, int t) {
#pragma unroll
    for (int i = 0; i < 4; i++) {
        int idx = t + i*256;
        int row = idx >> 3, seg = idx & 7;
        cpa16(asmb + (uint32_t)(row*144 + seg*16), A + (size_t)(mBase+row)*128 + k0 + seg*8);
    }
}

// ---------------- weight image prep (straight transposes) --------------------
__global__ void prep_all(const float* __restrict__ Wv, const float* __restrict__ P2,
                         const float* __restrict__ G2, const float* __restrict__ Wo,
                         __half* __restrict__ dst) {
    int y = blockIdx.y;                  // 0..4*LL-1
    int l = y >> 2, w = y & 3;
    const float* src;
    int slot;
    switch (w) {
        case 0: src = Wv; slot = 0; break;
        case 1: src = P2; slot = 3; break;
        case 2: src = G2; slot = 5; break;
        default: src = Wo; slot = 6; break;
    }
    src += (size_t)l*DD*DD;
    int n = blockIdx.x, k = threadIdx.x;
    dst[(size_t)(l*7 + slot)*16384 + n*128 + k] = __float2half(src[k*128 + n]);
}

// ---------------- composite weight prep: (A @ G1) images ---------------------
__global__ void prep_combo(const float* __restrict__ Wq, const float* __restrict__ Wk,
                           const float* __restrict__ P2, const float* __restrict__ G1,
                           __half* __restrict__ dst) {
    int n = blockIdx.x;
    int y = blockIdx.y;
    int l = y / 3, w = y % 3;
    const float* A = (w == 0 ? Wq : (w == 1 ? Wk : P2)) + (size_t)l*DD*DD;
    const float* B = G1 + (size_t)l*DD*DD;
    __shared__ float Bcol[DD];
    int k = threadIdx.x;
    Bcol[k] = B[k*DD + n];
    __syncthreads();
    float acc = 0.f;
#pragma unroll 8
    for (int c = 0; c < DD; c++) acc += A[k*DD + c] * Bcol[c];
    int slot = (w == 0 ? 1 : (w == 1 ? 2 : 4));
    dst[(size_t)(l*7 + slot)*16384 + n*DD + k] = __float2half(acc);
}

// ======================= fused GEMM: one A tile, 3 weights ==================
#define QKV_SMEM (6*4608*4)
__global__ __launch_bounds__(256, 2) void qkv3(const __half* __restrict__ A,
                                               const __half* __restrict__ B0,
                                               const __half* __restrict__ B1,
                                               const __half* __restrict__ B2,
                                               __half* __restrict__ O0,
                                               __half* __restrict__ O1,
                                               __half* __restrict__ O2) {
    extern __shared__ float sm[];
    uint32_t* Ast[2] = { (uint32_t*)sm, (uint32_t*)sm + 4608 };
    uint32_t* Bst[2] = { (uint32_t*)sm + 9216, (uint32_t*)sm + 13824 };
    int t = threadIdx.x;
    int mBase = blockIdx.x * 128;
    int lane = t & 31, wid = t >> 5;
    int r0 = (wid & 1) * 64, c0 = (wid >> 1) * 32;
    int ar = lane >> 2, ak = lane & 3;

    const __half* Bimg[3] = { B0, B1, B2 };
    __half* Out[3] = { O0, O1, O2 };
    uint32_t uA0 = smem_u32(Ast[0]), uA1 = smem_u32(Ast[1]);
    uint32_t uB0 = smem_u32(Bst[0]), uB1 = smem_u32(Bst[1]);

    loadA(uA0, A, mBase, 0, t);
    loadA(uA1, A, mBase, 64, t);
    loadB(uB0, B0, 0, t);
    cpa_commit();
    loadB(uB1, B0, 64, t);
    cpa_commit();

#pragma unroll
    for (int w = 0; w < 3; w++) {
        float acc[4][4][4] = {};
        cpa_wait<1>(); __syncthreads();
        mma_chunk16(uA0, 36, 0, uB0, r0, c0, lane, acc);
        __syncthreads();
        if (w < 2) { loadB(uB0, Bimg[w+1], 0, t); cpa_commit(); }
        if (w < 2) cpa_wait<1>(); else cpa_wait<0>();
        __syncthreads();
        mma_chunk16(uA1, 36, 0, uB1, r0, c0, lane, acc);
        __syncthreads();
        if (w < 2) { loadB(uB1, Bimg[w+1], 64, t); cpa_commit(); }
        __half* C = Out[w];
#pragma unroll
        for (int mf = 0; mf < 4; mf++)
#pragma unroll
        for (int nf = 0; nf < 4; nf++) {
            int r = mBase + r0 + mf*16 + ar;
            int c = c0 + nf*8 + 2*ak;
            *(__half2*)(C + (size_t)r*128 + c) =
                __floats2half2_rn(acc[mf][nf][0], acc[mf][nf][1]);
            *(__half2*)(C + (size_t)(r+8)*128 + c) =
                __floats2half2_rn(acc[mf][nf][2], acc[mf][nf][3]);
        }
    }
}

// ======================= residual GEMM: Cf = Res + A@W, Ch = half(Cf) =======
#define HG_SMEM (4*4608*4)
__global__ __launch_bounds__(256, 2) void hgemm_res(const __half* __restrict__ A,
                                                    const __half* __restrict__ Bimg,
                                                    __half* __restrict__ Ch,
                                                    float* __restrict__ Cf,
                                                    const float* __restrict__ Res) {
    extern __shared__ float sm[];
    uint32_t* Ast[2] = { (uint32_t*)sm, (uint32_t*)sm + 4608 };
    uint32_t* Bst[2] = { (uint32_t*)sm + 9216, (uint32_t*)sm + 13824 };
    int t = threadIdx.x;
    int mBase = blockIdx.x * 128;
    uint32_t uA0 = smem_u32(Ast[0]), uA1 = smem_u32(Ast[1]);
    uint32_t uB0 = smem_u32(Bst[0]), uB1 = smem_u32(Bst[1]);

    loadA(uA0, A, mBase, 0, t);
    loadB(uB0, Bimg, 0, t);
    cpa_commit();
    loadA(uA1, A, mBase, 64, t);
    loadB(uB1, Bimg, 64, t);
    cpa_commit();

    int lane = t & 31, wid = t >> 5;
    int r0 = (wid & 1) * 64, c0 = (wid >> 1) * 32;
    int ar = lane >> 2, ak = lane & 3;
    float acc[4][4][4] = {};

    cpa_wait<1>(); __syncthreads();
    mma_chunk16(uA0, 36, 0, uB0, r0, c0, lane, acc);
    cpa_wait<0>(); __syncthreads();
    mma_chunk16(uA1, 36, 0, uB1, r0, c0, lane, acc);

#pragma unroll
    for (int mf = 0; mf < 4; mf++)
#pragma unroll
    for (int nf = 0; nf < 4; nf++) {
        int r = mBase + r0 + mf*16 + ar;
        int c = c0 + nf*8 + 2*ak;
        float2 v0 = make_float2(acc[mf][nf][0], acc[mf][nf][1]);
        float2 v1 = make_float2(acc[mf][nf][2], acc[mf][nf][3]);
        float2 a0 = *(const float2*)(Res + (size_t)r*128 + c);
        float2 a1 = *(const float2*)(Res + (size_t)(r+8)*128 + c);
        v0.x += a0.x; v0.y += a0.y; v1.x += a1.x; v1.y += a1.y;
        *(float2*)(Cf + (size_t)r*128 + c) = v0;
        *(float2*)(Cf + (size_t)(r+8)*128 + c) = v1;
        *(__half2*)(Ch + (size_t)r*128 + c) = __floats2half2_rn(v0.x, v0.y);
        *(__half2*)(Ch + (size_t)(r+8)*128 + c) = __floats2half2_rn(v1.x, v1.y);
    }
}

// ======== fused per-neighbor block (linearity-restructured) =================
#define FU_SMEM (27136*4)
__global__ __launch_bounds__(256, 2) void pt_fused(const float* __restrict__ P1L,
                                                   const __half* __restrict__ P2img,
                                                   const __half* __restrict__ P21img,
                                                   const __half* __restrict__ G2img,
                                                   int mOff) {
    extern __shared__ float sm[];
    uint32_t* DlH = (uint32_t*)sm;
    uint32_t* Ast[2] = { (uint32_t*)(sm + 8704), (uint32_t*)(sm + 13312) };
    uint32_t* Bst[2] = { (uint32_t*)(sm + 17920), (uint32_t*)(sm + 22528) };
    float*    Ls = sm + 8704;

    __shared__ int     rowK[128];
    __shared__ __half2 relH[128][4];     // (x,x),(y,y),(z,z),pad
    __shared__ __half2 P1h[3][64];

    int t = threadIdx.x;
    int mBase = (blockIdx.x + mOff) * 128;
    int lane = t & 31, wid = t >> 5;
    int r0 = (wid & 1) * 64, c0 = (wid >> 1) * 32;
    int ar = lane >> 2, ak = lane & 3;
    uint32_t uA0 = smem_u32(Ast[0]), uA1 = smem_u32(Ast[1]);
    uint32_t uB0 = smem_u32(Bst[0]), uB1 = smem_u32(Bst[1]);
    uint32_t uHu = uA0;

    if (t < 128) {
        int m = mBase + t;
        rowK[t] = ((m >> 4) >> 12) * NN + g_idx[m];
        relH[t][0] = __float2half2_rn(g_rel[(size_t)m*3+0]);
        relH[t][1] = __float2half2_rn(g_rel[(size_t)m*3+1]);
        relH[t][2] = __float2half2_rn(g_rel[(size_t)m*3+2]);
    }
    if (t < 192) {
        int coord = t / 64, j = t % 64;
        P1h[coord][j] = __floats2half2_rn(P1L[coord*128 + 2*j], P1L[coord*128 + 2*j + 1]);
    }

    loadB(uB0, P2img, 0, t);  cpa_commit();
    loadB(uB1, P2img, 64, t); cpa_commit();
    __syncthreads();

    // ---- build A_pair = relu(rel @ P1) into Ast[0..1] (half2 math) ----
    {
        const __half2 z2 = __floats2half2_rn(0.f, 0.f);
#pragma unroll
        for (int st = 0; st < 2; st++) {
#pragma unroll
            for (int i = 0; i < 16; i++) {
                int idx = t + i*256;
                int row = idx >> 5, j = idx & 31;
                int pj = st*32 + j;
                __half2 v = __hmul2(relH[row][0], P1h[0][pj]);
                v = __hfma2(relH[row][1], P1h[1][pj], v);
                v = __hfma2(relH[row][2], P1h[2][pj], v);
                v = __hmax2(v, z2);
                Ast[st][row*36 + j] = h2u(v);
            }
        }
    }

    float acc[4][4][4] = {};

    // ================= GEMM A: delta = A_pair @ P2 -> DlH ===================
    cpa_wait<1>(); __syncthreads();
    mma_chunk16(uA0, 36, 0, uB0, r0, c0, lane, acc);
    __syncthreads();
    loadB(uB0, P21img, 0, t); cpa_commit();
    cpa_wait<1>(); __syncthreads();
    mma_chunk16(uA1, 36, 0, uB1, r0, c0, lane, acc);
    __syncthreads();
    loadB(uB1, P21img, 64, t); cpa_commit();
#pragma unroll
    for (int mf = 0; mf < 4; mf++)
#pragma unroll
    for (int nf = 0; nf < 4; nf++) {
        int r = r0 + mf*16 + ar;
        int cb = (c0 + nf*8) >> 1;
        DlH[r*68 + cb + ak] = h2u(__floats2half2_rn(acc[mf][nf][0], acc[mf][nf][1]));
        DlH[(r+8)*68 + cb + ak] = h2u(__floats2half2_rn(acc[mf][nf][2], acc[mf][nf][3]));
        acc[mf][nf][0] = acc[mf][nf][1] = acc[mf][nf][2] = acc[mf][nf][3] = 0.f;
    }

    // ================= GEMM B: dg = A_pair @ (P2 G1); h2 in epilogue ========
    cpa_wait<1>(); __syncthreads();
    mma_chunk16(uA0, 36, 0, uB0, r0, c0, lane, acc);
    __syncthreads();
    loadB(uB0, G2img, 0, t); cpa_commit();
    cpa_wait<1>(); __syncthreads();
    mma_chunk16(uA1, 36, 0, uB1, r0, c0, lane, acc);
    __syncthreads();
    loadB(uB1, G2img, 64, t); cpa_commit();
    {
        uint32_t* Hu = (uint32_t*)Ast[0];
#pragma unroll
        for (int mf = 0; mf < 4; mf++)
#pragma unroll
        for (int nf = 0; nf < 4; nf++) {
            int r = r0 + mf*16 + ar;
            int c = c0 + nf*8 + 2*ak;
            int bn0 = (mBase + r) >> 4, bn1 = (mBase + r + 8) >> 4;
            __half2 q0 = *(const __half2*)(g_qg + (size_t)bn0*128 + c);
            __half2 k0h = *(const __half2*)(g_kg + (size_t)rowK[r]*128 + c);
            __half2 q1 = *(const __half2*)(g_qg + (size_t)bn1*128 + c);
            __half2 k1h = *(const __half2*)(g_kg + (size_t)rowK[r+8]*128 + c);
            float h00 = fmaxf(acc[mf][nf][0] + __half2float(q0.x) - __half2float(k0h.x), 0.f);
            float h01 = fmaxf(acc[mf][nf][1] + __half2float(q0.y) - __half2float(k0h.y), 0.f);
            float h10 = fmaxf(acc[mf][nf][2] + __half2float(q1.x) - __half2float(k1h.x), 0.f);
            float h11 = fmaxf(acc[mf][nf][3] + __half2float(q1.y) - __half2float(k1h.y), 0.f);
            int cb = (c0 + nf*8) >> 1;
            Hu[r*68 + cb + ak] = h2u(__floats2half2_rn(h00, h01));
            Hu[(r+8)*68 + cb + ak] = h2u(__floats2half2_rn(h10, h11));
            acc[mf][nf][0] = acc[mf][nf][1] = acc[mf][nf][2] = acc[mf][nf][3] = 0.f;
        }
    }
    __syncthreads();

    // ================= GEMM C: logits = h2 @ G2 =============================
    cpa_wait<1>(); __syncthreads();
    mma_chunk16(uHu, 68, 0,  uB0, r0, c0, lane, acc);
    cpa_wait<0>(); __syncthreads();
    mma_chunk16(uHu, 68, 32, uB1, r0, c0, lane, acc);
    __syncthreads();
#pragma unroll
    for (int mf = 0; mf < 4; mf++)
#pragma unroll
    for (int nf = 0; nf < 4; nf++) {
        int r = r0 + mf*16 + ar;
        int c = c0 + nf*8 + 2*ak;
        Ls[r*132 + c]       = acc[mf][nf][0];
        Ls[r*132 + c+1]     = acc[mf][nf][1];
        Ls[(r+8)*132 + c]   = acc[mf][nf][2];
        Ls[(r+8)*132 + c+1] = acc[mf][nf][3];
    }
    __syncthreads();

    // ================= softmax over K + aggregate (2 dims/thread) ===========
    const __half* DlHh = (const __half*)DlH;
    for (int it = t; it < 512; it += 256) {
        int p = it >> 6, dd = (it & 63) * 2;
        float2 lo[KK];
        float mx0 = -3.4e38f, mx1 = -3.4e38f;
#pragma unroll
        for (int k = 0; k < KK; k++) {
            lo[k].x = Ls[(p*16 + k)*132 + dd];
            lo[k].y = Ls[(p*16 + k)*132 + dd + 1];
            mx0 = fmaxf(mx0, lo[k].x);
            mx1 = fmaxf(mx1, lo[k].y);
        }
        float s0 = 0.f, s1 = 0.f;
#pragma unroll
        for (int k = 0; k < KK; k++) {
            lo[k].x = expf(lo[k].x - mx0); s0 += lo[k].x;
            lo[k].y = expf(lo[k].y - mx1); s1 += lo[k].y;
        }
        float i0 = 1.f / s0, i1 = 1.f / s1;
        float a0 = 0.f, a1 = 0.f;
#pragma unroll
        for (int k = 0; k < KK; k++) {
            __half2 vj = *(const __half2*)(g_v + (size_t)rowK[p*16+k]*128 + dd);
            __half2 dl = *(const __half2*)(DlHh + (p*16 + k)*136 + dd);
            a0 += lo[k].x * i0 * (__half2float(vj.x) + __half2float(dl.x));
            a1 += lo[k].y * i1 * (__half2float(vj.y) + __half2float(dl.y));
        }
        *(__half2*)(g_agg + (size_t)((mBase >> 4) + p)*128 + dd) = __floats2half2_rn(a0, a1);
    }
}

// ---------------- embedding: x = relu(features @ W_embed) -------------------
__global__ void embed_k(const float* __restrict__ f, const float* __restrict__ W) {
    int m = blockIdx.x;
    int d = threadIdx.x;
    float f0 = f[m*3+0], f1 = f[m*3+1], f2 = f[m*3+2];
    float v = fmaxf(f0*W[d] + f1*W[DD+d] + f2*W[2*DD+d], 0.f);
    g_x[m*DD + d] = v;
    g_xh[m*DD + d] = __float2half(v);
}

// ---------------- kNN: 128-bin histogram select, half-batch launch ----------
// grid (NN/KQ, 4); batch = b0 + blockIdx.y
#define KQ 32
#define NBIN 128
__global__ __launch_bounds__(256) void knn_k(const float* __restrict__ pos, int b0) {
    __shared__ char smk[33280];
    float4*   sp   = (float4*)smk;                  // [1024] tile (16KB)
    uint32_t* hist = (uint32_t*)(smk + 16384);      // [32*128] (16KB)
    float*    bmD  = (float*)smk;                   // alias sp   [256*16]
    int*      bmI  = (int*)(smk + 16384);           // alias hist [256*16]
    uint32_t* qcnt = (uint32_t*)(smk + 32768);      // [32]
    int*      Tbin = (int*)(smk + 32896);           // [32]
    int*      Rrem = (int*)(smk + 33024);           // [32]

    int t = threadIdx.x;
    int b = b0 + blockIdx.y;
    int q = t >> 3, sub = t & 7;
    int qg = blockIdx.x*KQ + q;
    const float* pb = pos + (size_t)b*NN*3;
    float px = pb[qg*3+0], py = pb[qg*3+1], pz = pb[qg*3+2];
    float sqi = px*px + py*py + pz*pz;

    for (int i = t; i < KQ*NBIN; i += 256) hist[i] = 0;
    if (t < KQ) qcnt[t] = 0;
    __syncthreads();

    // ---- pass A: histogram (branchless) ----
    for (int j0 = 0; j0 < NN; j0 += 1024) {
        for (int i = t; i < 1024; i += 256) {
            float x = pb[(j0+i)*3+0], y = pb[(j0+i)*3+1], z = pb[(j0+i)*3+2];
            sp[i] = make_float4(-2.f*x, -2.f*y, -2.f*z, x*x + y*y + z*z);
        }
        __syncthreads();
#pragma unroll 4
        for (int s = 0; s < 1024; s += 8) {
            float4 c = sp[s + sub];
            float d2 = fmaf(px, c.x, c.w);
            d2 = fmaf(py, c.y, d2);
            d2 = fmaf(pz, c.z, d2);
            d2 = fmaxf(d2 + sqi, 0.f);
            int bin = (int)(__float_as_uint(d2) >> 20) - 952;
            bin = bin < 0 ? 0 : (bin > NBIN-1 ? NBIN-1 : bin);
            atomicAdd(&hist[q*NBIN + bin], 1u);
        }
        __syncthreads();
    }

    // ---- per-query threshold ----
    if (t < KQ) {
        int cum = 0, T = NBIN-1;
        for (int bn = 0; bn < NBIN; bn++) {
            int c = (int)hist[t*NBIN + bn];
            if (cum + c >= KK) { T = bn; break; }
            cum += c;
        }
        Tbin[t] = T;
        Rrem[t] = KK - cum;
    }
    __syncthreads();

    int T = Tbin[q];
    float bd[KK]; int bi[KK];
#pragma unroll
    for (int k = 0; k < KK; k++) { bd[k] = 3.4e38f; bi[k] = -1; }
    float worst = 3.4e38f; int wslot = 0;
    int base = (b*NN + qg)*KK;

    // ---- pass B: emit below-threshold; collect boundary top-16 ----
    for (int j0 = 0; j0 < NN; j0 += 1024) {
        for (int i = t; i < 1024; i += 256) {
            float x = pb[(j0+i)*3+0], y = pb[(j0+i)*3+1], z = pb[(j0+i)*3+2];
            sp[i] = make_float4(-2.f*x, -2.f*y, -2.f*z, x*x + y*y + z*z);
        }
        __syncthreads();
#pragma unroll 4
        for (int s = 0; s < 1024; s += 8) {
            float4 c = sp[s + sub];
            float d2 = fmaf(px, c.x, c.w);
            d2 = fmaf(py, c.y, d2);
            d2 = fmaf(pz, c.z, d2);
            d2 = fmaxf(d2 + sqi, 0.f);
            int bin = (int)(__float_as_uint(d2) >> 20) - 952;
            bin = bin < 0 ? 0 : (bin > NBIN-1 ? NBIN-1 : bin);
            if (bin < T) {
                uint32_t slot = atomicAdd(&qcnt[q], 1u);
                int j = j0 + s + sub;
                g_idx[base + slot] = j;
                g_rel[(size_t)(base+slot)*3+0] = fmaf(0.5f, c.x, px);
                g_rel[(size_t)(base+slot)*3+1] = fmaf(0.5f, c.y, py);
                g_rel[(size_t)(base+slot)*3+2] = fmaf(0.5f, c.z, pz);
            } else if (bin == T && d2 < worst) {
                bd[wslot] = d2; bi[wslot] = j0 + s + sub;
                worst = bd[0]; wslot = 0;
#pragma unroll
                for (int k = 1; k < KK; k++)
                    if (bd[k] > worst) { worst = bd[k]; wslot = k; }
            }
        }
        __syncthreads();
    }

    // ---- publish boundary lists (alias over sp/hist, both dead) ----
#pragma unroll
    for (int k = 0; k < KK; k++) {
        bmD[t*KK + k] = bd[k];
        bmI[t*KK + k] = bi[k];
    }
    __syncthreads();

    // ---- per-query merge: take R smallest of the 8 sub-lists (128 entries) --
    if (t < KQ) {
        int R = Rrem[t];
        int start = (int)qcnt[t];
        int qg2 = blockIdx.x*KQ + t;
        float qx = pb[qg2*3+0], qy = pb[qg2*3+1], qz = pb[qg2*3+2];
        int base2 = (b*NN + qg2)*KK;
        float* D = &bmD[t*128];
        int*   I = &bmI[t*128];
        for (int r = 0; r < R; r++) {
            float best = D[0]; int bl = 0;
#pragma unroll 8
            for (int k = 1; k < 128; k++)
                if (D[k] < best) { best = D[k]; bl = k; }
            int j = I[bl];
            D[bl] = 3.4e38f;
            g_idx[base2 + start + r] = j;
            g_rel[(size_t)(base2+start+r)*3+0] = qx - pb[j*3+0];
            g_rel[(size_t)(base2+start+r)*3+1] = qy - pb[j*3+1];
            g_rel[(size_t)(base2+start+r)*3+2] = qz - pb[j*3+2];
        }
    }
}

// ---------------- global max pool (partial) ---------------------------------
__global__ void poolmax_k() {
    int b  = blockIdx.x >> 5;
    int ch = blockIdx.x & 31;
    int d  = threadIdx.x;
    float m = -3.4e38f;
    for (int n = ch*128; n < ch*128 + 128; n++)
        m = fmaxf(m, g_x[((size_t)b*NN + n)*DD + d]);
    g_pmax[(size_t)blockIdx.x*DD + d] = m;
}

// ---------------- classifier head -------------------------------------------
__global__ void cls_k(const float* __restrict__ Wc1, const float* __restrict__ Wc2,
                      float* __restrict__ out) {
    int b = blockIdx.x;
    int d = threadIdx.x;
    __shared__ float pooled[DD];
    __shared__ float h[DD];
    float m = -3.4e38f;
    for (int ch = 0; ch < 32; ch++)
        m = fmaxf(m, g_pmax[((size_t)b*32 + ch)*DD + d]);
    pooled[d] = m;
    __syncthreads();
    float acc = 0.f;
    for (int c = 0; c < DD; c++) acc += pooled[c]*Wc1[c*DD + d];
    h[d] = fmaxf(acc, 0.f);
    __syncthreads();
    if (d < NCLS) {
        float o = 0.f;
        for (int c = 0; c < DD; c++) o += h[c]*Wc2[c*NCLS + d];
        out[b*NCLS + d] = o;
    }
}

// ---------------- launch -----------------------------------------------------
extern "C" void kernel_launch(void* const* d_in, const int* in_sizes, int n_in,
                              void* d_out, int out_size) {
    const float* features = (const float*)d_in[0];
    const float* pos      = (const float*)d_in[1];
    const float* W_embed  = (const float*)d_in[2];
    const float* Wq       = (const float*)d_in[3];
    const float* Wk       = (const float*)d_in[4];
    const float* Wv       = (const float*)d_in[5];
    const float* P1       = (const float*)d_in[6];
    const float* P2       = (const float*)d_in[7];
    const float* G1       = (const float*)d_in[8];
    const float* G2       = (const float*)d_in[9];
    const float* Wo       = (const float*)d_in[10];
    const float* Wc1      = (const float*)d_in[11];
    const float* Wc2      = (const float*)d_in[12];
    float* out = (float*)d_out;

    static float  *px = nullptr;
    static __half *pxh=nullptr, *pqg=nullptr, *pkg=nullptr, *pv=nullptr,
                  *pagg=nullptr, *pwimg=nullptr;
    static cudaStream_t sKnn = nullptr;
    static cudaEvent_t evFork = nullptr, evKnnH[2];
    if (!px) {
        cudaGetSymbolAddress((void**)&px,   g_x);
        cudaGetSymbolAddress((void**)&pxh,  g_xh);
        cudaGetSymbolAddress((void**)&pqg,  g_qg);
        cudaGetSymbolAddress((void**)&pkg,  g_kg);
        cudaGetSymbolAddress((void**)&pv,   g_v);
        cudaGetSymbolAddress((void**)&pagg, g_agg);
        cudaGetSymbolAddress((void**)&pwimg,g_wimg);
        cudaFuncSetAttribute(qkv3,      cudaFuncAttributeMaxDynamicSharedMemorySize, QKV_SMEM);
        cudaFuncSetAttribute(hgemm_res, cudaFuncAttributeMaxDynamicSharedMemorySize, HG_SMEM);
        cudaFuncSetAttribute(pt_fused,  cudaFuncAttributeMaxDynamicSharedMemorySize, FU_SMEM);
        cudaStreamCreateWithFlags(&sKnn, cudaStreamNonBlocking);
        cudaEventCreateWithFlags(&evFork, cudaEventDisableTiming);
        cudaEventCreateWithFlags(&evKnnH[0], cudaEventDisableTiming);
        cudaEventCreateWithFlags(&evKnnH[1], cudaEventDisableTiming);
    }

    // fork: two half-batch knn launches on the side stream
    cudaEventRecord(evFork, 0);
    cudaStreamWaitEvent(sKnn, evFork, 0);
    knn_k<<<dim3(NN/KQ, 4), 256, 0, sKnn>>>(pos, 0);
    cudaEventRecord(evKnnH[0], sKnn);
    knn_k<<<dim3(NN/KQ, 4), 256, 0, sKnn>>>(pos, 4);
    cudaEventRecord(evKnnH[1], sKnn);

    prep_all<<<dim3(128, 4*LL), 128>>>(Wv, P2, G2, Wo, pwimg);
    prep_combo<<<dim3(128, 3*LL), 128>>>(Wq, Wk, P2, G1, pwimg);
    embed_k<<<BN, DD>>>(features, W_embed);

    for (int l = 0; l < LL; l++) {
        const float*  P1L = P1 + (size_t)l*3*DD;
        const __half* img = pwimg + (size_t)l*7*16384;

        qkv3<<<BN/128, 256, QKV_SMEM>>>(pxh, img + 0*16384, img + 1*16384, img + 2*16384,
                                        pv, pqg, pkg);
        if (l == 0) {
            for (int h = 0; h < 2; h++) {
                cudaStreamWaitEvent(0, evKnnH[h], 0);
                pt_fused<<<MBIG/128/2, 256, FU_SMEM>>>(P1L, img + 3*16384,
                                                       img + 4*16384, img + 5*16384,
                                                       h * (MBIG/128/2));
            }
        } else {
            pt_fused<<<MBIG/128, 256, FU_SMEM>>>(P1L, img + 3*16384,
                                                 img + 4*16384, img + 5*16384, 0);
        }
        hgemm_res<<<BN/128, 256, HG_SMEM>>>(pagg, img + 6*16384, pxh, px, px);
    }

    poolmax_k<<<BB*32, DD>>>();
    cls_k<<<BB, DD>>>(Wc1, Wc2, out);
}